// round 3
// baseline (speedup 1.0000x reference)
#include <cuda_runtime.h>
#include <cuda_bf16.h>
#include <math.h>

// ---------------------------------------------------------------------------
// VariationalLinear fused kernel, round 3 (sm_100a)
//   out(256,4096) = x @ W^T + b,  W = mu + softplus(rho)*eps_w, + analytic KL
//
// R3 vs R2 (139.7us, latency-exposed: DRAM 30%, issue 31%, nothing saturated):
//  - 4-stage cp.async pipeline (lookahead ~3 chunks ~ 4000cy > DRAM latency)
//  - KC=8 so 4 stages x 2 CTAs fit SMEM (94KB/CTA)
//  - Wgen double-buffered; prefetch issued at earliest point after stage-ready
//  - one commit_group per chunk (empty near tail) keeps wait_group exact
// ---------------------------------------------------------------------------

#define BATCH   256
#define IN_F    4096
#define OUT_F   4096
#define NT      64
#define KSPLIT  4
#define KSEG    (IN_F / KSPLIT)    // 1024
#define KC      8
#define NCHUNK  (KSEG / KC)        // 128
#define STAGES  4
#define XSTRIDE 12                 // padded row stride (floats), conflict-free
#define THREADS 256

#define XS_STAGE  (BATCH * XSTRIDE)        // 3072 floats
#define RAW_STAGE (5 * NT * KC)            // 2560 floats
#define WG_ONE    (NT * XSTRIDE)           // 768 floats
#define SMEM_FLOATS (STAGES * XS_STAGE + STAGES * RAW_STAGE + 2 * WG_ONE)
#define SMEM_BYTES  (SMEM_FLOATS * 4)      // 96256 B

__device__ __align__(16) float g_x_tf32[BATCH * IN_F];

__device__ __forceinline__ unsigned cvt_tf32(float x) {
    unsigned r;
    asm volatile("cvt.rna.tf32.f32 %0, %1;" : "=r"(r) : "f"(x));
    return r;
}

__device__ __forceinline__ void cp_async16(void* smem_dst, const void* gsrc) {
    unsigned saddr = (unsigned)__cvta_generic_to_shared(smem_dst);
    asm volatile("cp.async.cg.shared.global [%0], [%1], 16;"
                 :: "r"(saddr), "l"(gsrc));
}

__device__ __forceinline__ void mma_tf32(float* c, const unsigned* a,
                                         unsigned b0, unsigned b1) {
    asm volatile(
        "mma.sync.aligned.m16n8k8.row.col.f32.tf32.tf32.f32 "
        "{%0,%1,%2,%3}, {%4,%5,%6,%7}, {%8,%9}, {%0,%1,%2,%3};"
        : "+f"(c[0]), "+f"(c[1]), "+f"(c[2]), "+f"(c[3])
        : "r"(a[0]), "r"(a[1]), "r"(a[2]), "r"(a[3]), "r"(b0), "r"(b1));
}

__device__ __forceinline__ float softplus_fast(float r) {
    return (r > 15.f) ? r : __logf(1.f + __expf(r));
}

// ---------------------------------------------------------------------------
// Prep: out <- bias broadcast, KL slot <- 0, x -> tf32 scratch.
// ---------------------------------------------------------------------------
__global__ void vl_prep(const float* __restrict__ x,
                        const float* __restrict__ bmu,
                        const float* __restrict__ brho,
                        const float* __restrict__ epsb,
                        float* __restrict__ out, int out_size) {
    int i = blockIdx.x * blockDim.x + threadIdx.x;
    if (i < BATCH * OUT_F) {
        int col = i & (OUT_F - 1);
        out[i] = fmaf(softplus_fast(brho[col]), epsb[col], bmu[col]);
    } else if (i < out_size) {
        out[i] = 0.f;
    }
    if (i < BATCH * IN_F)
        g_x_tf32[i] = __uint_as_float(cvt_tf32(x[i]));
}

// ---------------------------------------------------------------------------
// Main fused kernel
// ---------------------------------------------------------------------------
__global__ void __launch_bounds__(THREADS, 2)
vl_main(const float* __restrict__ mu, const float* __restrict__ rho,
        const float* __restrict__ epsw, const float* __restrict__ pmu,
        const float* __restrict__ psig,
        float* __restrict__ out, float* __restrict__ klout) {
    extern __shared__ float sm[];
    float* Xs   = sm;                                  // [STAGES][256][XSTRIDE]
    float* Raw  = sm + STAGES * XS_STAGE;              // [STAGES][5][NT*KC]
    float* Wgen = sm + STAGES * (XS_STAGE + RAW_STAGE); // [2][NT][XSTRIDE]
    __shared__ float klred[8];

    const int tid  = threadIdx.x;
    const int warp = tid >> 5;
    const int lane = tid & 31;
    const int g    = lane >> 2;
    const int t    = lane & 3;

    const int ntile = blockIdx.x >> 2;
    const int kseg  = blockIdx.x & 3;
    const int n0    = ntile * NT;
    const int kbase = kseg * KSEG;

    float acc[2][8][4];
#pragma unroll
    for (int mt = 0; mt < 2; mt++)
#pragma unroll
        for (int nt = 0; nt < 8; nt++)
#pragma unroll
            for (int i = 0; i < 4; i++) acc[mt][nt][i] = 0.f;

    float klsum = 0.f;

    // X staging: 512 float4 per stage, 2 per thread. f = tid + 256*i
    // row = f>>1, seg = f&1 (two float4 per 8-float row)
    // Raw staging: 640 float4 per stage: f = tid (+256,+512<640)
    // stream = f>>7, idx = f&127 -> row = idx>>1, seg = idx&1
    const float* streams[5] = { mu, rho, epsw, pmu, psig };

    auto prefetch = [&](int c) {
        if (c >= NCHUNK) return;
        const int st = c & (STAGES - 1);
        const int k0 = kbase + c * KC;
        float* xd = Xs + st * XS_STAGE;
#pragma unroll
        for (int i = 0; i < 2; i++) {
            int f   = tid + THREADS * i;     // 0..511
            int row = f >> 1;
            int seg = f & 1;
            cp_async16(xd + row * XSTRIDE + seg * 4,
                       g_x_tf32 + (long)row * IN_F + k0 + seg * 4);
        }
        float* rd = Raw + st * RAW_STAGE;
#pragma unroll
        for (int i = 0; i < 3; i++) {
            int f = tid + THREADS * i;       // 0..767, use <640
            if (f < 640) {
                int s   = f >> 7;            // stream 0..4
                int idx = f & 127;
                int row = idx >> 1;
                int seg = idx & 1;
                cp_async16(rd + s * (NT * KC) + idx * 4,
                           streams[s] + (long)(n0 + row) * IN_F + k0 + seg * 4);
            }
        }
    };

    // prologue: stage chunks 0..2
#pragma unroll
    for (int p = 0; p < STAGES - 1; p++) {
        prefetch(p);
        asm volatile("cp.async.commit_group;");
    }

    // Wgen indexing: thread handles 2 consecutive elements
    const int we   = tid * 2;                // element 0..510
    const int wrow = we >> 3;                // 0..63
    const int wk   = we & 7;

    for (int c = 0; c < NCHUNK; c++) {
        const int st = c & (STAGES - 1);
        asm volatile("cp.async.wait_group 2;");
        __syncthreads();                     // stage st ready & safe to refill st of c+3

        // earliest possible issue of chunk c+3 loads
        prefetch(c + STAGES - 1);
        asm volatile("cp.async.commit_group;");

        // ---- generate W (tf32) + KL: 2 elements per thread ----
        {
            const float* rb = Raw + st * RAW_STAGE;
            float2 m2 = *reinterpret_cast<const float2*>(rb + 0 * NT * KC + we);
            float2 r2 = *reinterpret_cast<const float2*>(rb + 1 * NT * KC + we);
            float2 e2 = *reinterpret_cast<const float2*>(rb + 2 * NT * KC + we);
            float2 p2 = *reinterpret_cast<const float2*>(rb + 3 * NT * KC + we);
            float2 s2 = *reinterpret_cast<const float2*>(rb + 4 * NT * KC + we);
            const float mv[2] = {m2.x, m2.y};
            const float rv[2] = {r2.x, r2.y};
            const float ev[2] = {e2.x, e2.y};
            const float pv[2] = {p2.x, p2.y};
            const float sv[2] = {s2.x, s2.y};
            float wv[2];
#pragma unroll
            for (int q = 0; q < 2; q++) {
                float sg = softplus_fast(rv[q]);
                float w  = fmaf(sg, ev[q], mv[q]);
                wv[q] = __uint_as_float(cvt_tf32(w));
                float d   = mv[q] - pv[q];
                float ps2 = sv[q] * sv[q];
                klsum += __logf(sv[q]) - __logf(sg)
                       + __fdividef(0.5f * fmaf(sg, sg, d * d), ps2)
                       - 0.5f;
            }
            float* wb = Wgen + (c & 1) * WG_ONE;
            *reinterpret_cast<float2*>(wb + wrow * XSTRIDE + wk) =
                make_float2(wv[0], wv[1]);
        }
        __syncthreads();                     // Wgen[c&1] visible

        // ---- tf32 MMA over the KC=8 chunk ----
        const float* Xc = Xs + st * XS_STAGE + warp * 32 * XSTRIDE;
        const float* Wc = Wgen + (c & 1) * WG_ONE;
        unsigned a0[4], a1[4];
        const float* A0 = Xc + t;
        a0[0] = __float_as_uint(A0[g * XSTRIDE]);
        a0[1] = __float_as_uint(A0[(g + 8) * XSTRIDE]);
        a0[2] = __float_as_uint(A0[g * XSTRIDE + 4]);
        a0[3] = __float_as_uint(A0[(g + 8) * XSTRIDE + 4]);
        const float* A1 = A0 + 16 * XSTRIDE;
        a1[0] = __float_as_uint(A1[g * XSTRIDE]);
        a1[1] = __float_as_uint(A1[(g + 8) * XSTRIDE]);
        a1[2] = __float_as_uint(A1[g * XSTRIDE + 4]);
        a1[3] = __float_as_uint(A1[(g + 8) * XSTRIDE + 4]);
#pragma unroll
        for (int nt = 0; nt < 8; nt++) {
            const float* Bp = Wc + (nt * 8 + g) * XSTRIDE + t;
            unsigned b0 = __float_as_uint(Bp[0]);
            unsigned b1 = __float_as_uint(Bp[4]);
            mma_tf32(acc[0][nt], a0, b0, b1);
            mma_tf32(acc[1][nt], a1, b0, b1);
        }
    }

    // ---- epilogue: atomic-accumulate partial output ----
#pragma unroll
    for (int mt = 0; mt < 2; mt++) {
        int r0 = warp * 32 + mt * 16 + g;
#pragma unroll
        for (int nt = 0; nt < 8; nt++) {
            int col = n0 + nt * 8 + 2 * t;
            atomicAdd(&out[(long)r0 * OUT_F + col],           acc[mt][nt][0]);
            atomicAdd(&out[(long)r0 * OUT_F + col + 1],       acc[mt][nt][1]);
            atomicAdd(&out[(long)(r0 + 8) * OUT_F + col],     acc[mt][nt][2]);
            atomicAdd(&out[(long)(r0 + 8) * OUT_F + col + 1], acc[mt][nt][3]);
        }
    }

    // ---- KL reduction ----
#pragma unroll
    for (int o = 16; o; o >>= 1)
        klsum += __shfl_xor_sync(0xFFFFFFFFu, klsum, o);
    if (lane == 0) klred[warp] = klsum;
    __syncthreads();
    if (tid == 0) {
        float s = 0.f;
#pragma unroll
        for (int i = 0; i < 8; i++) s += klred[i];
        atomicAdd(klout, s);
    }
}

// ---------------------------------------------------------------------------
extern "C" void kernel_launch(void* const* d_in, const int* in_sizes, int n_in,
                              void* d_out, int out_size) {
    const float* x    = (const float*)d_in[0];
    const float* wmu  = (const float*)d_in[1];
    const float* wrho = (const float*)d_in[2];
    const float* bmu  = (const float*)d_in[3];
    const float* brho = (const float*)d_in[4];
    const float* epsw = (const float*)d_in[5];
    const float* epsb = (const float*)d_in[6];
    const float* pmu  = (const float*)d_in[7];
    const float* psig = (const float*)d_in[8];
    float* out = (float*)d_out;

    int n = BATCH * IN_F;
    if (out_size > n) n = out_size;
    vl_prep<<<(n + 255) / 256, 256>>>(x, bmu, brho, epsb, out, out_size);

    cudaFuncSetAttribute(vl_main, cudaFuncAttributeMaxDynamicSharedMemorySize,
                         SMEM_BYTES);
    vl_main<<<(OUT_F / NT) * KSPLIT, THREADS, SMEM_BYTES>>>(
        wmu, wrho, epsw, pmu, psig, out, out + (out_size - 1));
}

// round 4
// speedup vs baseline: 1.2172x; 1.2172x over previous
#include <cuda_runtime.h>
#include <cuda_bf16.h>
#include <math.h>

// ---------------------------------------------------------------------------
// VariationalLinear fused kernel, round 4 (sm_100a)
//   out(256,4096) = x @ W^T + b,  W = mu + softplus(rho)*eps_w, + analytic KL
//
// R4 vs R2 (139.7us) / R3 (180us, regression from tiny chunks):
//  - X evicted from SMEM: prep writes tf32 k-major transpose xT[k][b] to a
//    4MB scratch; MMA A-fragments are coalesced LDGs from L2 (slice L2-hot,
//    shared by 64 CTAs).
//  - freed SMEM -> 4-stage weight pipeline at KC=16 (wait_group 2 = ~3-chunk
//    lookahead) with the SAME per-chunk overhead as R2 (64 chunks, 2 syncs).
//  - single Wgen buffer (top-of-chunk barrier orders reuse).
// ---------------------------------------------------------------------------

#define BATCH   256
#define IN_F    4096
#define OUT_F   4096
#define NT      64
#define KSPLIT  4
#define KSEG    (IN_F / KSPLIT)    // 1024
#define KC      16
#define NCHUNK  (KSEG / KC)        // 64
#define STAGES  4
#define WSTRIDE 20                 // Wgen padded row stride (floats)
#define THREADS 256

#define RAW_STAGE (5 * NT * KC)            // 5120 floats = 20KB
#define WG_SIZE   (NT * WSTRIDE)           // 1280 floats = 5KB
#define SMEM_FLOATS (STAGES * RAW_STAGE + WG_SIZE)
#define SMEM_BYTES  (SMEM_FLOATS * 4)      // 87040 B -> 2 CTAs/SM

__device__ __align__(16) float g_xT[IN_F * BATCH];   // tf32, k-major

__device__ __forceinline__ unsigned cvt_tf32(float x) {
    unsigned r;
    asm volatile("cvt.rna.tf32.f32 %0, %1;" : "=r"(r) : "f"(x));
    return r;
}

__device__ __forceinline__ void cp_async16(void* smem_dst, const void* gsrc) {
    unsigned saddr = (unsigned)__cvta_generic_to_shared(smem_dst);
    asm volatile("cp.async.cg.shared.global [%0], [%1], 16;"
                 :: "r"(saddr), "l"(gsrc));
}

__device__ __forceinline__ void mma_tf32(float* c, const unsigned* a,
                                         unsigned b0, unsigned b1) {
    asm volatile(
        "mma.sync.aligned.m16n8k8.row.col.f32.tf32.tf32.f32 "
        "{%0,%1,%2,%3}, {%4,%5,%6,%7}, {%8,%9}, {%0,%1,%2,%3};"
        : "+f"(c[0]), "+f"(c[1]), "+f"(c[2]), "+f"(c[3])
        : "r"(a[0]), "r"(a[1]), "r"(a[2]), "r"(a[3]), "r"(b0), "r"(b1));
}

__device__ __forceinline__ float softplus_fast(float r) {
    return (r > 15.f) ? r : __logf(1.f + __expf(r));
}

// ---------------------------------------------------------------------------
// Prep A: out <- bias broadcast, KL slot <- 0.
// ---------------------------------------------------------------------------
__global__ void vl_bias(const float* __restrict__ bmu,
                        const float* __restrict__ brho,
                        const float* __restrict__ epsb,
                        float* __restrict__ out, int out_size) {
    int i = blockIdx.x * blockDim.x + threadIdx.x;
    if (i < BATCH * OUT_F) {
        int col = i & (OUT_F - 1);
        out[i] = fmaf(softplus_fast(brho[col]), epsb[col], bmu[col]);
    } else if (i < out_size) {
        out[i] = 0.f;
    }
}

// ---------------------------------------------------------------------------
// Prep B: tiled transpose x(256,4096) -> xT(4096,256), tf32-rounded.
// grid (IN_F/32, BATCH/32), block (32,8)
// ---------------------------------------------------------------------------
__global__ void vl_xt(const float* __restrict__ x) {
    __shared__ float tile[32][33];
    int k0 = blockIdx.x * 32;
    int b0 = blockIdx.y * 32;
#pragma unroll
    for (int j = threadIdx.y; j < 32; j += 8)
        tile[j][threadIdx.x] = x[(long)(b0 + j) * IN_F + k0 + threadIdx.x];
    __syncthreads();
#pragma unroll
    for (int j = threadIdx.y; j < 32; j += 8)
        g_xT[(long)(k0 + j) * BATCH + b0 + threadIdx.x] =
            __uint_as_float(cvt_tf32(tile[threadIdx.x][j]));
}

// ---------------------------------------------------------------------------
// Main fused kernel
// ---------------------------------------------------------------------------
__global__ void __launch_bounds__(THREADS, 2)
vl_main(const float* __restrict__ mu, const float* __restrict__ rho,
        const float* __restrict__ epsw, const float* __restrict__ pmu,
        const float* __restrict__ psig,
        float* __restrict__ out, float* __restrict__ klout) {
    extern __shared__ float sm[];
    float* Raw  = sm;                          // [STAGES][5][NT*KC]
    float* Wgen = sm + STAGES * RAW_STAGE;     // [NT][WSTRIDE]
    __shared__ float klred[8];

    const int tid  = threadIdx.x;
    const int warp = tid >> 5;
    const int lane = tid & 31;
    const int g    = lane >> 2;                // 0..7
    const int t    = lane & 3;                 // 0..3

    const int ntile = blockIdx.x >> 2;
    const int kseg  = blockIdx.x & 3;
    const int n0    = ntile * NT;
    const int kbase = kseg * KSEG;

    const int m32 = warp * 32;                 // warp's M-row block
    const float* __restrict__ Xb = g_xT + m32;

    float acc[2][8][4];
#pragma unroll
    for (int mt = 0; mt < 2; mt++)
#pragma unroll
        for (int nt = 0; nt < 8; nt++)
#pragma unroll
            for (int i = 0; i < 4; i++) acc[mt][nt][i] = 0.f;

    float klsum = 0.f;

    // weight staging: thread owns one float4 per stream per chunk
    const int wrow = tid >> 2;                 // 0..63
    const int wseg = tid & 3;                  // 0..3
    const long wg_gofs = (long)(n0 + wrow) * IN_F + kbase + wseg * 4;
    const int  raw_t   = tid * 4;

    const float* streams[5] = { mu, rho, epsw, pmu, psig };

    auto prefetch = [&](int c) {
        if (c >= NCHUNK) return;
        const int st = c & (STAGES - 1);
        const int k0 = c * KC;
        float* rd = Raw + st * RAW_STAGE;
#pragma unroll
        for (int s = 0; s < 5; s++) {
            cp_async16(rd + s * (NT * KC) + raw_t,
                       streams[s] + wg_gofs + k0);
        }
    };

    // prologue: stage chunks 0..2
#pragma unroll
    for (int p = 0; p < STAGES - 1; p++) {
        prefetch(p);
        asm volatile("cp.async.commit_group;");
    }

    for (int c = 0; c < NCHUNK; c++) {
        const int st = c & (STAGES - 1);
        asm volatile("cp.async.wait_group 2;");
        __syncthreads();    // Raw[st] ready; stage (c+3)&3 reusable

        prefetch(c + STAGES - 1);
        asm volatile("cp.async.commit_group;");

        // ---- A fragments for this chunk: coalesced LDGs from L2 (early) ----
        unsigned af[2][8];
        const int kk = kbase + c * KC;
#pragma unroll
        for (int ks = 0; ks < 2; ks++) {
            const float* P  = Xb + (long)(kk + ks * 8 + t) * BATCH;
            const float* P4 = P + 4 * BATCH;
            af[ks][0] = __float_as_uint(P[g]);
            af[ks][1] = __float_as_uint(P[g + 8]);
            af[ks][2] = __float_as_uint(P4[g]);
            af[ks][3] = __float_as_uint(P4[g + 8]);
            af[ks][4] = __float_as_uint(P[g + 16]);
            af[ks][5] = __float_as_uint(P[g + 24]);
            af[ks][6] = __float_as_uint(P4[g + 16]);
            af[ks][7] = __float_as_uint(P4[g + 24]);
        }

        // ---- generate W (tf32) + KL: one float4 per thread ----
        {
            const float* rb = Raw + st * RAW_STAGE;
            float4 m4 = *reinterpret_cast<const float4*>(rb + 0 * NT * KC + raw_t);
            float4 r4 = *reinterpret_cast<const float4*>(rb + 1 * NT * KC + raw_t);
            float4 e4 = *reinterpret_cast<const float4*>(rb + 2 * NT * KC + raw_t);
            float4 p4 = *reinterpret_cast<const float4*>(rb + 3 * NT * KC + raw_t);
            float4 s4 = *reinterpret_cast<const float4*>(rb + 4 * NT * KC + raw_t);
            const float mv[4] = {m4.x, m4.y, m4.z, m4.w};
            const float rv[4] = {r4.x, r4.y, r4.z, r4.w};
            const float ev[4] = {e4.x, e4.y, e4.z, e4.w};
            const float pv[4] = {p4.x, p4.y, p4.z, p4.w};
            const float sv[4] = {s4.x, s4.y, s4.z, s4.w};
            float wv[4];
#pragma unroll
            for (int q = 0; q < 4; q++) {
                float sg = softplus_fast(rv[q]);
                float w  = fmaf(sg, ev[q], mv[q]);
                wv[q] = __uint_as_float(cvt_tf32(w));
                float d   = mv[q] - pv[q];
                float ps2 = sv[q] * sv[q];
                klsum += __logf(sv[q]) - __logf(sg)
                       + __fdividef(0.5f * fmaf(sg, sg, d * d), ps2)
                       - 0.5f;
            }
            *reinterpret_cast<float4*>(Wgen + wrow * WSTRIDE + wseg * 4) =
                make_float4(wv[0], wv[1], wv[2], wv[3]);
        }
        __syncthreads();    // Wgen visible

        // ---- tf32 MMA over the KC=16 chunk ----
#pragma unroll
        for (int ks = 0; ks < 2; ks++) {
            const int kb = ks * 8;
#pragma unroll
            for (int nt = 0; nt < 8; nt++) {
                const float* Bp = Wgen + (nt * 8 + g) * WSTRIDE + kb + t;
                unsigned b0 = __float_as_uint(Bp[0]);
                unsigned b1 = __float_as_uint(Bp[4]);
                mma_tf32(acc[0][nt], &af[ks][0], b0, b1);
                mma_tf32(acc[1][nt], &af[ks][4], b0, b1);
            }
        }
        // no trailing sync: next top-of-loop __syncthreads orders Wgen reuse
    }

    // ---- epilogue: atomic-accumulate partial output (bias already in out) ----
#pragma unroll
    for (int mt = 0; mt < 2; mt++) {
        int r0 = m32 + mt * 16 + g;
#pragma unroll
        for (int nt = 0; nt < 8; nt++) {
            int col = n0 + nt * 8 + 2 * t;
            atomicAdd(&out[(long)r0 * OUT_F + col],           acc[mt][nt][0]);
            atomicAdd(&out[(long)r0 * OUT_F + col + 1],       acc[mt][nt][1]);
            atomicAdd(&out[(long)(r0 + 8) * OUT_F + col],     acc[mt][nt][2]);
            atomicAdd(&out[(long)(r0 + 8) * OUT_F + col + 1], acc[mt][nt][3]);
        }
    }

    // ---- KL reduction ----
#pragma unroll
    for (int o = 16; o; o >>= 1)
        klsum += __shfl_xor_sync(0xFFFFFFFFu, klsum, o);
    if (lane == 0) klred[warp] = klsum;
    __syncthreads();
    if (tid == 0) {
        float s = 0.f;
#pragma unroll
        for (int i = 0; i < 8; i++) s += klred[i];
        atomicAdd(klout, s);
    }
}

// ---------------------------------------------------------------------------
extern "C" void kernel_launch(void* const* d_in, const int* in_sizes, int n_in,
                              void* d_out, int out_size) {
    const float* x    = (const float*)d_in[0];
    const float* wmu  = (const float*)d_in[1];
    const float* wrho = (const float*)d_in[2];
    const float* bmu  = (const float*)d_in[3];
    const float* brho = (const float*)d_in[4];
    const float* epsw = (const float*)d_in[5];
    const float* epsb = (const float*)d_in[6];
    const float* pmu  = (const float*)d_in[7];
    const float* psig = (const float*)d_in[8];
    float* out = (float*)d_out;

    vl_bias<<<(out_size + 255) / 256, 256>>>(bmu, brho, epsb, out, out_size);

    dim3 tg(IN_F / 32, BATCH / 32);
    vl_xt<<<tg, dim3(32, 8)>>>(x);

    cudaFuncSetAttribute(vl_main, cudaFuncAttributeMaxDynamicSharedMemorySize,
                         SMEM_BYTES);
    vl_main<<<(OUT_F / NT) * KSPLIT, THREADS, SMEM_BYTES>>>(
        wmu, wrho, epsw, pmu, psig, out, out + (out_size - 1));
}

// round 6
// speedup vs baseline: 1.6560x; 1.3605x over previous
#include <cuda_runtime.h>
#include <cuda_fp16.h>
#include <math.h>

// ---------------------------------------------------------------------------
// VariationalLinear fused kernel, round 6 (= R5 rerun; infra failed last time)
//   out(256,4096) = x @ W^T + b,  W = mu + softplus(rho)*eps_w, + analytic KL
//
// R2 skeleton (best: 139.7us) with fp16 m16n8k16 datapath:
//  - fp16 mantissa == tf32 mantissa (10 bits) -> same accuracy, fp32 accum
//  - per-chunk MMA instrs 32->16, fragment LDS 48->24, X SMEM halves
//  - freed SMEM -> 3-stage pipeline at KC=16 (2 chunks in flight in compute)
//  - same 64 chunks, same 2 syncthreads/chunk as R2
// ---------------------------------------------------------------------------

#define BATCH   256
#define IN_F    4096
#define OUT_F   4096
#define NT      64
#define KSPLIT  4
#define KSEG    (IN_F / KSPLIT)    // 1024
#define KC      16
#define NCHUNK  (KSEG / KC)        // 64
#define STAGES  3
#define XSH     24                 // X row stride in halves (16 data + pad)
#define WSH     24                 // Wgen row stride in halves
#define THREADS 256

#define XS_STAGE_H  (BATCH * XSH)          // 6144 halves = 12KB
#define RAW_STAGE_F (5 * NT * KC)          // 5120 floats = 20KB
#define WG_H        (NT * WSH)             // 1536 halves = 3KB
// bytes: X 3*12288 + raw 3*20480 + Wgen 3072 = 101376
#define SMEM_BYTES  (STAGES * XS_STAGE_H * 2 + STAGES * RAW_STAGE_F * 4 + WG_H * 2)

__device__ __align__(16) __half g_x_h[BATCH * IN_F];   // x in fp16, row-major

__device__ __forceinline__ void cp_async16(void* smem_dst, const void* gsrc) {
    unsigned saddr = (unsigned)__cvta_generic_to_shared(smem_dst);
    asm volatile("cp.async.cg.shared.global [%0], [%1], 16;"
                 :: "r"(saddr), "l"(gsrc));
}

__device__ __forceinline__ void mma_f16(float* c, const unsigned* a,
                                        unsigned b0, unsigned b1) {
    asm volatile(
        "mma.sync.aligned.m16n8k16.row.col.f32.f16.f16.f32 "
        "{%0,%1,%2,%3}, {%4,%5,%6,%7}, {%8,%9}, {%0,%1,%2,%3};"
        : "+f"(c[0]), "+f"(c[1]), "+f"(c[2]), "+f"(c[3])
        : "r"(a[0]), "r"(a[1]), "r"(a[2]), "r"(a[3]), "r"(b0), "r"(b1));
}

__device__ __forceinline__ float softplus_fast(float r) {
    return (r > 15.f) ? r : __logf(1.f + __expf(r));
}

// ---------------------------------------------------------------------------
// Prep: out <- bias broadcast, KL slot <- 0, x -> fp16 scratch.
// ---------------------------------------------------------------------------
__global__ void vl_prep(const float* __restrict__ x,
                        const float* __restrict__ bmu,
                        const float* __restrict__ brho,
                        const float* __restrict__ epsb,
                        float* __restrict__ out, int out_size) {
    int i = blockIdx.x * blockDim.x + threadIdx.x;
    if (i < BATCH * OUT_F) {
        int col = i & (OUT_F - 1);
        out[i] = fmaf(softplus_fast(brho[col]), epsb[col], bmu[col]);
    } else if (i < out_size) {
        out[i] = 0.f;
    }
    if (i < BATCH * IN_F)
        g_x_h[i] = __float2half_rn(x[i]);
}

// ---------------------------------------------------------------------------
// Main fused kernel
// ---------------------------------------------------------------------------
__global__ void __launch_bounds__(THREADS, 2)
vl_main(const float* __restrict__ mu, const float* __restrict__ rho,
        const float* __restrict__ epsw, const float* __restrict__ pmu,
        const float* __restrict__ psig,
        float* __restrict__ out, float* __restrict__ klout) {
    extern __shared__ char smbase[];
    __half* Xs  = (__half*)smbase;                             // [3][256][XSH]
    float*  Raw = (float*)(smbase + STAGES * XS_STAGE_H * 2);  // [3][5][NT*KC]
    __half* Wg  = (__half*)(smbase + STAGES * XS_STAGE_H * 2
                                   + STAGES * RAW_STAGE_F * 4); // [NT][WSH]
    __shared__ float klred[8];

    const int tid  = threadIdx.x;
    const int warp = tid >> 5;
    const int lane = tid & 31;
    const int g    = lane >> 2;                // 0..7
    const int t    = lane & 3;                 // 0..3

    const int ntile = blockIdx.x >> 2;
    const int kseg  = blockIdx.x & 3;
    const int n0    = ntile * NT;
    const int kbase = kseg * KSEG;
    const int m32   = warp * 32;

    float acc[2][8][4];
#pragma unroll
    for (int mt = 0; mt < 2; mt++)
#pragma unroll
        for (int nt = 0; nt < 8; nt++)
#pragma unroll
            for (int i = 0; i < 4; i++) acc[mt][nt][i] = 0.f;

    float klsum = 0.f;

    // weight staging: thread owns one float4 per stream per chunk
    const int wrow = tid >> 2;                 // 0..63
    const int wseg = tid & 3;                  // 0..3
    const long wg_gofs = (long)(n0 + wrow) * IN_F + kbase + wseg * 4;
    const int  raw_t   = tid * 4;

    const float* streams[5] = { mu, rho, epsw, pmu, psig };

    auto prefetch = [&](int c) {               // stage chunk c -> buffers c%3
        if (c < NCHUNK) {
            const int st = c % STAGES;
            const int k0 = c * KC;
            // X: 256 rows x 16 halves = 512 x 16B, 2 per thread
            __half* xd = Xs + st * XS_STAGE_H;
#pragma unroll
            for (int i = 0; i < 2; i++) {
                int f   = tid + THREADS * i;   // 0..511
                int row = f >> 1;
                int seg = f & 1;
                cp_async16(xd + row * XSH + seg * 8,
                           g_x_h + (long)row * IN_F + kbase + k0 + seg * 8);
            }
            // 5 weight streams: one float4 per stream per thread
            float* rd = Raw + st * RAW_STAGE_F;
#pragma unroll
            for (int s = 0; s < 5; s++)
                cp_async16(rd + s * (NT * KC) + raw_t, streams[s] + wg_gofs + k0);
        }
        asm volatile("cp.async.commit_group;");
    };

    // prologue: stage chunks 0,1
    prefetch(0);
    prefetch(1);

    for (int c = 0; c < NCHUNK; c++) {
        const int st = c % STAGES;
        asm volatile("cp.async.wait_group 1;");   // chunk c landed
        __syncthreads();                          // all threads done chunk c-1

        prefetch(c + 2);                          // refill stage (c+2)%3

        // ---- generate W (fp16) + KL: one float4 per thread ----
        {
            const float* rb = Raw + st * RAW_STAGE_F;
            float4 m4 = *reinterpret_cast<const float4*>(rb + 0 * NT * KC + raw_t);
            float4 r4 = *reinterpret_cast<const float4*>(rb + 1 * NT * KC + raw_t);
            float4 e4 = *reinterpret_cast<const float4*>(rb + 2 * NT * KC + raw_t);
            float4 p4 = *reinterpret_cast<const float4*>(rb + 3 * NT * KC + raw_t);
            float4 s4 = *reinterpret_cast<const float4*>(rb + 4 * NT * KC + raw_t);
            const float mv[4] = {m4.x, m4.y, m4.z, m4.w};
            const float rv[4] = {r4.x, r4.y, r4.z, r4.w};
            const float ev[4] = {e4.x, e4.y, e4.z, e4.w};
            const float pv[4] = {p4.x, p4.y, p4.z, p4.w};
            const float sv[4] = {s4.x, s4.y, s4.z, s4.w};
            float wv[4];
#pragma unroll
            for (int q = 0; q < 4; q++) {
                float sg = softplus_fast(rv[q]);
                wv[q] = fmaf(sg, ev[q], mv[q]);
                float d   = mv[q] - pv[q];
                float ps2 = sv[q] * sv[q];
                klsum += __logf(sv[q]) - __logf(sg)
                       + __fdividef(0.5f * fmaf(sg, sg, d * d), ps2)
                       - 0.5f;
            }
            __half2 p0 = __floats2half2_rn(wv[0], wv[1]);
            __half2 p1 = __floats2half2_rn(wv[2], wv[3]);
            __half2* wp = reinterpret_cast<__half2*>(Wg + wrow * WSH + wseg * 4);
            wp[0] = p0;
            wp[1] = p1;
        }
        __syncthreads();                          // Wg visible

        // ---- fp16 MMA over the KC=16 chunk (single k16 step) ----
        const __half* Xc = Xs + st * XS_STAGE_H;
        unsigned a0[4], a1[4];
        {
            const __half* R0 = Xc + (long)(m32 + g) * XSH + 2 * t;
            a0[0] = *reinterpret_cast<const unsigned*>(R0);
            a0[1] = *reinterpret_cast<const unsigned*>(R0 + 8 * XSH);
            a0[2] = *reinterpret_cast<const unsigned*>(R0 + 8);
            a0[3] = *reinterpret_cast<const unsigned*>(R0 + 8 * XSH + 8);
            const __half* R1 = R0 + 16 * XSH;
            a1[0] = *reinterpret_cast<const unsigned*>(R1);
            a1[1] = *reinterpret_cast<const unsigned*>(R1 + 8 * XSH);
            a1[2] = *reinterpret_cast<const unsigned*>(R1 + 8);
            a1[3] = *reinterpret_cast<const unsigned*>(R1 + 8 * XSH + 8);
        }
#pragma unroll
        for (int nt = 0; nt < 8; nt++) {
            const __half* Bp = Wg + (nt * 8 + g) * WSH + 2 * t;
            unsigned b0 = *reinterpret_cast<const unsigned*>(Bp);
            unsigned b1 = *reinterpret_cast<const unsigned*>(Bp + 8);
            mma_f16(acc[0][nt], a0, b0, b1);
            mma_f16(acc[1][nt], a1, b0, b1);
        }
        // next top-of-loop barrier orders Wg + stage reuse
    }

    // ---- epilogue: atomic-accumulate partial output (bias already in out) ----
#pragma unroll
    for (int mt = 0; mt < 2; mt++) {
        int r0 = m32 + mt * 16 + g;
#pragma unroll
        for (int nt = 0; nt < 8; nt++) {
            int col = n0 + nt * 8 + 2 * t;
            atomicAdd(&out[(long)r0 * OUT_F + col],           acc[mt][nt][0]);
            atomicAdd(&out[(long)r0 * OUT_F + col + 1],       acc[mt][nt][1]);
            atomicAdd(&out[(long)(r0 + 8) * OUT_F + col],     acc[mt][nt][2]);
            atomicAdd(&out[(long)(r0 + 8) * OUT_F + col + 1], acc[mt][nt][3]);
        }
    }

    // ---- KL reduction ----
#pragma unroll
    for (int o = 16; o; o >>= 1)
        klsum += __shfl_xor_sync(0xFFFFFFFFu, klsum, o);
    if (lane == 0) klred[warp] = klsum;
    __syncthreads();
    if (tid == 0) {
        float s = 0.f;
#pragma unroll
        for (int i = 0; i < 8; i++) s += klred[i];
        atomicAdd(klout, s);
    }
}

// ---------------------------------------------------------------------------
extern "C" void kernel_launch(void* const* d_in, const int* in_sizes, int n_in,
                              void* d_out, int out_size) {
    const float* x    = (const float*)d_in[0];
    const float* wmu  = (const float*)d_in[1];
    const float* wrho = (const float*)d_in[2];
    const float* bmu  = (const float*)d_in[3];
    const float* brho = (const float*)d_in[4];
    const float* epsw = (const float*)d_in[5];
    const float* epsb = (const float*)d_in[6];
    const float* pmu  = (const float*)d_in[7];
    const float* psig = (const float*)d_in[8];
    float* out = (float*)d_out;

    int n = BATCH * IN_F;
    if (out_size > n) n = out_size;
    vl_prep<<<(n + 255) / 256, 256>>>(x, bmu, brho, epsb, out, out_size);

    cudaFuncSetAttribute(vl_main, cudaFuncAttributeMaxDynamicSharedMemorySize,
                         SMEM_BYTES);
    vl_main<<<(OUT_F / NT) * KSPLIT, THREADS, SMEM_BYTES>>>(
        wmu, wrho, epsw, pmu, psig, out, out + (out_size - 1));
}